// round 2
// baseline (speedup 1.0000x reference)
#include <cuda_runtime.h>
#include <cuda_bf16.h>

// Problem constants (fixed shapes per reference)
#define N_NODES_MAX 50000
#define HF 64

// Scratch tables: A[n] = h[n] @ W1[0:64,:] + b1, B[n] = h[n] @ W1[64:128,:]
__device__ float gA[N_NODES_MAX * HF];
__device__ float gB[N_NODES_MAX * HF];

// ---------------------------------------------------------------------------
// Kernel 1: per-node precompute.  C[n, jj] = sum_k h[n,k] * W1[k + 64*(jj>=64), jj&63]
// Tile: 64 nodes x 128 output-cols, K=64 (single pass). 256 threads, 4x8 per thread.
// ---------------------------------------------------------------------------
__global__ __launch_bounds__(256) void node_precompute(
    const float* __restrict__ h,
    const float* __restrict__ W1,
    const float* __restrict__ b1,
    int n_nodes)
{
    __shared__ float sh[64 * 64];    // sh[m][k]
    __shared__ float sW[64 * 128];   // sW[k][jj]

    const int t = threadIdx.x;
    const int node0 = blockIdx.x * 64;

    // W1 combined layout sW[k][jj]; jj<64 -> top half (A), jj>=64 -> bottom half (B)
    for (int i = t; i < 64 * 128; i += 256) {
        int k  = i >> 7;
        int jj = i & 127;
        sW[i] = W1[(k + (jj & 64)) * 64 + (jj & 63)];
    }
    for (int i = t; i < 64 * 64; i += 256) {
        int m = i >> 6;
        int k = i & 63;
        int n = node0 + m;
        sh[i] = (n < n_nodes) ? h[n * 64 + k] : 0.f;
    }
    __syncthreads();

    const int tx = t & 15;   // jj0 = tx*8 (tx<8 -> A half, tx>=8 -> B half)
    const int ty = t >> 4;   // m0  = ty*4

    float acc[4][8];
#pragma unroll
    for (int m = 0; m < 4; m++)
#pragma unroll
        for (int j = 0; j < 8; j++) acc[m][j] = 0.f;

#pragma unroll 8
    for (int k = 0; k < 64; k++) {
        float a[4];
#pragma unroll
        for (int m = 0; m < 4; m++) a[m] = sh[(ty * 4 + m) * 64 + k];
        const float4 w0 = *reinterpret_cast<const float4*>(&sW[k * 128 + tx * 8]);
        const float4 w1 = *reinterpret_cast<const float4*>(&sW[k * 128 + tx * 8 + 4]);
#pragma unroll
        for (int m = 0; m < 4; m++) {
            acc[m][0] = fmaf(a[m], w0.x, acc[m][0]);
            acc[m][1] = fmaf(a[m], w0.y, acc[m][1]);
            acc[m][2] = fmaf(a[m], w0.z, acc[m][2]);
            acc[m][3] = fmaf(a[m], w0.w, acc[m][3]);
            acc[m][4] = fmaf(a[m], w1.x, acc[m][4]);
            acc[m][5] = fmaf(a[m], w1.y, acc[m][5]);
            acc[m][6] = fmaf(a[m], w1.z, acc[m][6]);
            acc[m][7] = fmaf(a[m], w1.w, acc[m][7]);
        }
    }

    const int jj0 = tx * 8;
    const bool isA = (jj0 < 64);
    float bb[8];
#pragma unroll
    for (int j = 0; j < 8; j++) bb[j] = isA ? __ldg(&b1[jj0 + j]) : 0.f;

#pragma unroll
    for (int m = 0; m < 4; m++) {
        int n = node0 + ty * 4 + m;
        if (n >= n_nodes) break;
        float* dst = isA ? (&gA[n * 64 + jj0]) : (&gB[n * 64 + (jj0 - 64)]);
        float4 o0 = make_float4(acc[m][0] + bb[0], acc[m][1] + bb[1],
                                acc[m][2] + bb[2], acc[m][3] + bb[3]);
        float4 o1 = make_float4(acc[m][4] + bb[4], acc[m][5] + bb[5],
                                acc[m][6] + bb[6], acc[m][7] + bb[7]);
        *reinterpret_cast<float4*>(dst)     = o0;
        *reinterpret_cast<float4*>(dst + 4) = o1;
    }
}

// ---------------------------------------------------------------------------
// Kernel 2: per-edge scoring. One warp per edge.
// score = W2 . relu(A[src] + B[dst]) + b2 ; label = rint(sigmoid(score))
// Indices are int32 (harness downcasts the reference's int64).
// ---------------------------------------------------------------------------
__global__ __launch_bounds__(256) void edge_score(
    const int* __restrict__ src,
    const int* __restrict__ dst,
    const float* __restrict__ W2,
    const float* __restrict__ b2,
    float* __restrict__ out,
    int n_edges, int n_nodes)
{
    const int gw   = (blockIdx.x * blockDim.x + threadIdx.x) >> 5;  // warp-uniform edge id
    const int lane = threadIdx.x & 31;
    if (gw >= n_edges) return;

    int s = __ldg(&src[gw]);
    int d = __ldg(&dst[gw]);
    // Defensive clamp (no-op if indices are valid)
    s = min(max(s, 0), n_nodes - 1);
    d = min(max(d, 0), n_nodes - 1);

    const float2 a = __ldg(reinterpret_cast<const float2*>(gA + (size_t)s * 64) + lane);
    const float2 b = __ldg(reinterpret_cast<const float2*>(gB + (size_t)d * 64) + lane);
    const float2 w = __ldg(reinterpret_cast<const float2*>(W2) + lane);

    const float v0 = fmaxf(a.x + b.x, 0.f);
    const float v1 = fmaxf(a.y + b.y, 0.f);
    float p = v0 * w.x + v1 * w.y;

#pragma unroll
    for (int off = 16; off > 0; off >>= 1)
        p += __shfl_xor_sync(0xFFFFFFFFu, p, off);

    if (lane == 0) {
        const float sc = p + __ldg(&b2[0]);
        out[gw] = sc;
        // label = round(sigmoid(score)); rintf = round-half-even, matching jnp.round
        const float sig = 1.f / (1.f + expf(-sc));
        out[n_edges + gw] = rintf(sig);
    }
}

// ---------------------------------------------------------------------------
// Launch: inputs in order h, src, dst, W1, b1, W2, b2
// ---------------------------------------------------------------------------
extern "C" void kernel_launch(void* const* d_in, const int* in_sizes, int n_in,
                              void* d_out, int out_size)
{
    const float* h   = (const float*)d_in[0];
    const int*   src = (const int*)d_in[1];
    const int*   dst = (const int*)d_in[2];
    const float* W1  = (const float*)d_in[3];
    const float* b1  = (const float*)d_in[4];
    const float* W2  = (const float*)d_in[5];
    const float* b2  = (const float*)d_in[6];
    float* out = (float*)d_out;

    const int n_nodes = in_sizes[0] / HF;
    const int n_edges = in_sizes[1];

    const int blocks1 = (n_nodes + 63) / 64;
    node_precompute<<<blocks1, 256>>>(h, W1, b1, n_nodes);

    const long long total_threads = (long long)n_edges * 32;
    const int blocks2 = (int)((total_threads + 255) / 256);
    edge_score<<<blocks2, 256>>>(src, dst, W2, b2, out, n_edges, n_nodes);
}

// round 3
// speedup vs baseline: 2.0913x; 2.0913x over previous
#include <cuda_runtime.h>
#include <cuda_bf16.h>

#define N_NODES_MAX 50000
#define HF 64

// Scratch tables: A[n] = h[n] @ W1[0:64,:] + b1, B[n] = h[n] @ W1[64:128,:]
__device__ float gA[N_NODES_MAX * HF];
__device__ float gB[N_NODES_MAX * HF];

// ---------------------------------------------------------------------------
// Kernel 1: per-node precompute (64 nodes x 128 cols tile, 256 thr, 4x8/thread)
// ---------------------------------------------------------------------------
__global__ __launch_bounds__(256) void node_precompute(
    const float* __restrict__ h,
    const float* __restrict__ W1,
    const float* __restrict__ b1,
    int n_nodes)
{
    __shared__ float sh[64 * 64];
    __shared__ float sW[64 * 128];

    const int t = threadIdx.x;
    const int node0 = blockIdx.x * 64;

    for (int i = t; i < 64 * 128; i += 256) {
        int k  = i >> 7;
        int jj = i & 127;
        sW[i] = W1[(k + (jj & 64)) * 64 + (jj & 63)];
    }
    for (int i = t; i < 64 * 64; i += 256) {
        int m = i >> 6;
        int k = i & 63;
        int n = node0 + m;
        sh[i] = (n < n_nodes) ? h[n * 64 + k] : 0.f;
    }
    __syncthreads();

    const int tx = t & 15;
    const int ty = t >> 4;

    float acc[4][8];
#pragma unroll
    for (int m = 0; m < 4; m++)
#pragma unroll
        for (int j = 0; j < 8; j++) acc[m][j] = 0.f;

#pragma unroll 8
    for (int k = 0; k < 64; k++) {
        float a[4];
#pragma unroll
        for (int m = 0; m < 4; m++) a[m] = sh[(ty * 4 + m) * 64 + k];
        const float4 w0 = *reinterpret_cast<const float4*>(&sW[k * 128 + tx * 8]);
        const float4 w1 = *reinterpret_cast<const float4*>(&sW[k * 128 + tx * 8 + 4]);
#pragma unroll
        for (int m = 0; m < 4; m++) {
            acc[m][0] = fmaf(a[m], w0.x, acc[m][0]);
            acc[m][1] = fmaf(a[m], w0.y, acc[m][1]);
            acc[m][2] = fmaf(a[m], w0.z, acc[m][2]);
            acc[m][3] = fmaf(a[m], w0.w, acc[m][3]);
            acc[m][4] = fmaf(a[m], w1.x, acc[m][4]);
            acc[m][5] = fmaf(a[m], w1.y, acc[m][5]);
            acc[m][6] = fmaf(a[m], w1.z, acc[m][6]);
            acc[m][7] = fmaf(a[m], w1.w, acc[m][7]);
        }
    }

    const int jj0 = tx * 8;
    const bool isA = (jj0 < 64);
    float bb[8];
#pragma unroll
    for (int j = 0; j < 8; j++) bb[j] = isA ? __ldg(&b1[jj0 + j]) : 0.f;

#pragma unroll
    for (int m = 0; m < 4; m++) {
        int n = node0 + ty * 4 + m;
        if (n >= n_nodes) break;
        float* dst = isA ? (&gA[n * 64 + jj0]) : (&gB[n * 64 + (jj0 - 64)]);
        float4 o0 = make_float4(acc[m][0] + bb[0], acc[m][1] + bb[1],
                                acc[m][2] + bb[2], acc[m][3] + bb[3]);
        float4 o1 = make_float4(acc[m][4] + bb[4], acc[m][5] + bb[5],
                                acc[m][6] + bb[6], acc[m][7] + bb[7]);
        *reinterpret_cast<float4*>(dst)     = o0;
        *reinterpret_cast<float4*>(dst + 4) = o1;
    }
}

// ---------------------------------------------------------------------------
// Kernel 2: per-edge scoring. 8 lanes per edge, 4 edges per warp.
// Each lane: 2x float4 from A-row + 2x float4 from B-row (one full 128B line
// per LDG.128 per group), 16 fma terms, 3-shuffle width-8 reduction.
// ---------------------------------------------------------------------------
__global__ __launch_bounds__(256) void edge_score(
    const int* __restrict__ src,
    const int* __restrict__ dst,
    const float* __restrict__ W2,
    const float* __restrict__ b2,
    float* __restrict__ out,
    int n_edges, int n_nodes)
{
    const int tid  = blockIdx.x * blockDim.x + threadIdx.x;
    const int lane = threadIdx.x & 31;
    const int gl   = lane & 7;              // lane within 8-lane group
    const int e    = tid >> 3;              // edge id (one per 8-lane group)
    if (e >= n_edges) return;

    int s = __ldg(&src[e]);
    int d = __ldg(&dst[e]);
    s = min(max(s, 0), n_nodes - 1);
    d = min(max(d, 0), n_nodes - 1);

    // W2 in registers: lane gl covers j = gl*4..gl*4+3 and 32+gl*4..32+gl*4+3
    const float4 w0 = __ldg(reinterpret_cast<const float4*>(W2) + gl);
    const float4 w1 = __ldg(reinterpret_cast<const float4*>(W2) + gl + 8);

    const float4* pa = reinterpret_cast<const float4*>(gA + (size_t)s * HF) + gl;
    const float4* pb = reinterpret_cast<const float4*>(gB + (size_t)d * HF) + gl;
    const float4 a0 = __ldg(pa);
    const float4 a1 = __ldg(pa + 8);
    const float4 b0 = __ldg(pb);
    const float4 b1 = __ldg(pb + 8);

    float p;
    p  =        fmaxf(a0.x + b0.x, 0.f) * w0.x;
    p  = fmaf(  fmaxf(a0.y + b0.y, 0.f), w0.y, p);
    p  = fmaf(  fmaxf(a0.z + b0.z, 0.f), w0.z, p);
    p  = fmaf(  fmaxf(a0.w + b0.w, 0.f), w0.w, p);
    p  = fmaf(  fmaxf(a1.x + b1.x, 0.f), w1.x, p);
    p  = fmaf(  fmaxf(a1.y + b1.y, 0.f), w1.y, p);
    p  = fmaf(  fmaxf(a1.z + b1.z, 0.f), w1.z, p);
    p  = fmaf(  fmaxf(a1.w + b1.w, 0.f), w1.w, p);

    // width-8 reduction
    p += __shfl_xor_sync(0xFFFFFFFFu, p, 4);
    p += __shfl_xor_sync(0xFFFFFFFFu, p, 2);
    p += __shfl_xor_sync(0xFFFFFFFFu, p, 1);

    if (gl == 0) {
        const float sc = p + __ldg(&b2[0]);
        out[e] = sc;
        const float sig = 1.f / (1.f + expf(-sc));
        out[n_edges + e] = rintf(sig);   // round-half-even, matches jnp.round
    }
}

// ---------------------------------------------------------------------------
// Launch: inputs in order h, src, dst, W1, b1, W2, b2
// ---------------------------------------------------------------------------
extern "C" void kernel_launch(void* const* d_in, const int* in_sizes, int n_in,
                              void* d_out, int out_size)
{
    const float* h   = (const float*)d_in[0];
    const int*   src = (const int*)d_in[1];
    const int*   dst = (const int*)d_in[2];
    const float* W1  = (const float*)d_in[3];
    const float* b1  = (const float*)d_in[4];
    const float* W2  = (const float*)d_in[5];
    const float* b2  = (const float*)d_in[6];
    float* out = (float*)d_out;

    const int n_nodes = in_sizes[0] / HF;
    const int n_edges = in_sizes[1];

    const int blocks1 = (n_nodes + 63) / 64;
    node_precompute<<<blocks1, 256>>>(h, W1, b1, n_nodes);

    const long long total_threads = (long long)n_edges * 8;   // 8 lanes per edge
    const int blocks2 = (int)((total_threads + 255) / 256);
    edge_score<<<blocks2, 256>>>(src, dst, W2, b2, out, n_edges, n_nodes);
}